// round 1
// baseline (speedup 1.0000x reference)
#include <cuda_runtime.h>

#define N_NODES 100000
#define HD 128
#define IN_DIM 256
#define LN_EPS 1e-5f

// ---------------- scratch (device globals; no allocation allowed) ----------------
__device__ __align__(16) float g_hu[(size_t)N_NODES * HD];
__device__ __align__(16) float g_hi[(size_t)N_NODES * HD];
__device__ __align__(16) float g_agg_u[(size_t)N_NODES * HD];
__device__ __align__(16) float g_agg_i[(size_t)N_NODES * HD];
__device__ __align__(16) float g_tmp_u[(size_t)N_NODES * HD];
__device__ __align__(16) float g_tmp_i[(size_t)N_NODES * HD];
__device__ __align__(16) float g_cnt_u[N_NODES];
__device__ __align__(16) float g_cnt_i[N_NODES];

// ---------------- zero agg/cnt for a layer ----------------
__global__ void zero_layer_kernel() {
    const size_t n4 = (size_t)N_NODES * HD / 4;
    const float4 z = make_float4(0.f, 0.f, 0.f, 0.f);
    float4* au = (float4*)g_agg_u;
    float4* ai = (float4*)g_agg_i;
    float4* cu = (float4*)g_cnt_u;
    float4* ci = (float4*)g_cnt_i;
    size_t stride = (size_t)gridDim.x * blockDim.x;
    for (size_t i = (size_t)blockIdx.x * blockDim.x + threadIdx.x; i < n4; i += stride) {
        au[i] = z;
        ai[i] = z;
        if (i < N_NODES / 4) { cu[i] = z; ci[i] = z; }
    }
}

// ---------------- edge scatter: warp per edge, float4 per lane ----------------
__global__ __launch_bounds__(256) void scatter_kernel(
    const int* __restrict__ src, const int* __restrict__ dst, int E, int to_item)
{
    const float* h = to_item ? g_hu : g_hi;   // source features
    float* agg     = to_item ? g_agg_i : g_agg_u;
    float* cnt     = to_item ? g_cnt_i : g_cnt_u;

    int w = (blockIdx.x * blockDim.x + threadIdx.x) >> 5;
    int lane = threadIdx.x & 31;
    if (w >= E) return;
    int s = src[w];
    int d = dst[w];
    float4 v = ((const float4*)(h + (size_t)s * HD))[lane];
    float* ap = agg + (size_t)d * HD + lane * 4;
    atomicAdd(ap + 0, v.x);
    atomicAdd(ap + 1, v.y);
    atomicAdd(ap + 2, v.z);
    atomicAdd(ap + 3, v.w);
    if (lane == 0) atomicAdd(cnt + d, 1.0f);
}

// ---------------- cnt -> 1/max(cnt,1) in place (both sides) ----------------
__global__ void rinv_kernel(int N) {
    int i = blockIdx.x * blockDim.x + threadIdx.x;
    if (i < N) {
        g_cnt_u[i] = 1.0f / fmaxf(g_cnt_u[i], 1.0f);
        g_cnt_i[i] = 1.0f / fmaxf(g_cnt_i[i], 1.0f);
    }
}

// ---------------- input projection GEMM: C = relu(A[N,256] @ W[128,256]^T + b) --------
// classic 128x128 tile, BK=8, TM=TN=8, 256 threads
__global__ __launch_bounds__(256) void proj_gemm_kernel(
    const float* __restrict__ A, const float* __restrict__ W,
    const float* __restrict__ bias, int N, int to_user)
{
    __shared__ __align__(16) float As[8][128];
    __shared__ __align__(16) float Ws[8][128];
    float* C = to_user ? g_hu : g_hi;

    int tid = threadIdx.x;
    int tx = tid & 15, ty = tid >> 4;
    int row0 = blockIdx.x * 128;
    int lrow = tid >> 1;          // 0..127
    int lcol = (tid & 1) * 4;     // 0 or 4

    float acc[8][8];
#pragma unroll
    for (int i = 0; i < 8; i++)
#pragma unroll
        for (int j = 0; j < 8; j++) acc[i][j] = 0.f;

    int gr = row0 + lrow;
    bool rok = gr < N;
    const float* Arow = A + (size_t)gr * IN_DIM;
    const float* Wrow = W + (size_t)lrow * IN_DIM;

    for (int k0 = 0; k0 < IN_DIM; k0 += 8) {
        float4 av = rok ? *(const float4*)(Arow + k0 + lcol) : make_float4(0, 0, 0, 0);
        float4 wv = *(const float4*)(Wrow + k0 + lcol);
        As[lcol + 0][lrow] = av.x; As[lcol + 1][lrow] = av.y;
        As[lcol + 2][lrow] = av.z; As[lcol + 3][lrow] = av.w;
        Ws[lcol + 0][lrow] = wv.x; Ws[lcol + 1][lrow] = wv.y;
        Ws[lcol + 2][lrow] = wv.z; Ws[lcol + 3][lrow] = wv.w;
        __syncthreads();
#pragma unroll
        for (int kk = 0; kk < 8; kk++) {
            float4 a0 = *(const float4*)&As[kk][ty * 8];
            float4 a1 = *(const float4*)&As[kk][ty * 8 + 4];
            float4 b0 = *(const float4*)&Ws[kk][tx * 8];
            float4 b1 = *(const float4*)&Ws[kk][tx * 8 + 4];
            float ra[8] = {a0.x, a0.y, a0.z, a0.w, a1.x, a1.y, a1.z, a1.w};
            float rb[8] = {b0.x, b0.y, b0.z, b0.w, b1.x, b1.y, b1.z, b1.w};
#pragma unroll
            for (int i = 0; i < 8; i++)
#pragma unroll
                for (int j = 0; j < 8; j++) acc[i][j] += ra[i] * rb[j];
        }
        __syncthreads();
    }

#pragma unroll
    for (int i = 0; i < 8; i++) {
        int r = row0 + ty * 8 + i;
        if (r >= N) continue;
#pragma unroll
        for (int j = 0; j < 8; j++) {
            int c = tx * 8 + j;
            float v = acc[i][j] + bias[c];
            v = fmaxf(v, 0.f);   // projection always has relu
            C[(size_t)r * HD + c] = v;
        }
    }
}

// ---------------- SAGE combine GEMM ----------------
// C = (agg * rinv) @ WL^T + h @ WR^T + BL   (virtual K=256 concat)
__global__ __launch_bounds__(256) void sage_gemm_kernel(
    const float* __restrict__ WL, const float* __restrict__ WR,
    const float* __restrict__ BL, int N, int to_item)
{
    __shared__ __align__(16) float As[8][128];
    __shared__ __align__(16) float Ws[8][128];

    const float* A0   = to_item ? g_agg_i : g_agg_u;
    const float* RINV = to_item ? g_cnt_i : g_cnt_u;   // already inverted
    const float* A1   = to_item ? g_hi : g_hu;
    float* C          = to_item ? g_tmp_i : g_tmp_u;

    int tid = threadIdx.x;
    int tx = tid & 15, ty = tid >> 4;
    int row0 = blockIdx.x * 128;
    int lrow = tid >> 1;
    int lcol = (tid & 1) * 4;

    float acc[8][8];
#pragma unroll
    for (int i = 0; i < 8; i++)
#pragma unroll
        for (int j = 0; j < 8; j++) acc[i][j] = 0.f;

    int gr = row0 + lrow;
    bool rok = gr < N;
    float rscale = rok ? RINV[gr] : 0.f;
    const float* A0row = A0 + (size_t)gr * HD;
    const float* A1row = A1 + (size_t)gr * HD;
    const float* WLrow = WL + (size_t)lrow * HD;
    const float* WRrow = WR + (size_t)lrow * HD;

    for (int k0 = 0; k0 < 256; k0 += 8) {
        float4 av, wv;
        if (k0 < 128) {
            av = rok ? *(const float4*)(A0row + k0 + lcol) : make_float4(0, 0, 0, 0);
            av.x *= rscale; av.y *= rscale; av.z *= rscale; av.w *= rscale;
            wv = *(const float4*)(WLrow + k0 + lcol);
        } else {
            av = rok ? *(const float4*)(A1row + (k0 - 128) + lcol) : make_float4(0, 0, 0, 0);
            wv = *(const float4*)(WRrow + (k0 - 128) + lcol);
        }
        As[lcol + 0][lrow] = av.x; As[lcol + 1][lrow] = av.y;
        As[lcol + 2][lrow] = av.z; As[lcol + 3][lrow] = av.w;
        Ws[lcol + 0][lrow] = wv.x; Ws[lcol + 1][lrow] = wv.y;
        Ws[lcol + 2][lrow] = wv.z; Ws[lcol + 3][lrow] = wv.w;
        __syncthreads();
#pragma unroll
        for (int kk = 0; kk < 8; kk++) {
            float4 a0 = *(const float4*)&As[kk][ty * 8];
            float4 a1 = *(const float4*)&As[kk][ty * 8 + 4];
            float4 b0 = *(const float4*)&Ws[kk][tx * 8];
            float4 b1 = *(const float4*)&Ws[kk][tx * 8 + 4];
            float ra[8] = {a0.x, a0.y, a0.z, a0.w, a1.x, a1.y, a1.z, a1.w};
            float rb[8] = {b0.x, b0.y, b0.z, b0.w, b1.x, b1.y, b1.z, b1.w};
#pragma unroll
            for (int i = 0; i < 8; i++)
#pragma unroll
                for (int j = 0; j < 8; j++) acc[i][j] += ra[i] * rb[j];
        }
        __syncthreads();
    }

#pragma unroll
    for (int i = 0; i < 8; i++) {
        int r = row0 + ty * 8 + i;
        if (r >= N) continue;
#pragma unroll
        for (int j = 0; j < 8; j++) {
            int c = tx * 8 + j;
            C[(size_t)r * HD + c] = acc[i][j] + BL[c];
        }
    }
}

// ---------------- residual + LayerNorm (+optional relu); warp per row ----------------
__global__ __launch_bounds__(256) void ln_kernel(
    const float* __restrict__ gamma, const float* __restrict__ beta,
    float* out_override, int N, int relu, int user_side)
{
    const float* h = user_side ? g_hu : g_hi;
    const float* t = user_side ? g_tmp_u : g_tmp_i;
    float* o = out_override ? out_override : (user_side ? g_hu : g_hi);

    int row = (blockIdx.x * blockDim.x + threadIdx.x) >> 5;
    int lane = threadIdx.x & 31;
    if (row >= N) return;

    float4 hv = ((const float4*)(h + (size_t)row * HD))[lane];
    float4 tv = ((const float4*)(t + (size_t)row * HD))[lane];
    float v0 = hv.x + tv.x, v1 = hv.y + tv.y, v2 = hv.z + tv.z, v3 = hv.w + tv.w;

    float s = v0 + v1 + v2 + v3;
#pragma unroll
    for (int off = 16; off; off >>= 1) s += __shfl_xor_sync(0xffffffffu, s, off);
    float mu = s * (1.0f / 128.0f);
    v0 -= mu; v1 -= mu; v2 -= mu; v3 -= mu;

    float q = v0 * v0 + v1 * v1 + v2 * v2 + v3 * v3;
#pragma unroll
    for (int off = 16; off; off >>= 1) q += __shfl_xor_sync(0xffffffffu, q, off);
    float rs = rsqrtf(q * (1.0f / 128.0f) + LN_EPS);

    float4 gv = ((const float4*)gamma)[lane];
    float4 bv = ((const float4*)beta)[lane];
    float o0 = v0 * rs * gv.x + bv.x;
    float o1 = v1 * rs * gv.y + bv.y;
    float o2 = v2 * rs * gv.z + bv.z;
    float o3 = v3 * rs * gv.w + bv.w;
    if (relu) {
        o0 = fmaxf(o0, 0.f); o1 = fmaxf(o1, 0.f);
        o2 = fmaxf(o2, 0.f); o3 = fmaxf(o3, 0.f);
    }
    ((float4*)(o + (size_t)row * HD))[lane] = make_float4(o0, o1, o2, o3);
}

// ---------------- launch ----------------
extern "C" void kernel_launch(void* const* d_in, const int* in_sizes, int n_in,
                              void* d_out, int out_size)
{
    const float* x_user = (const float*)d_in[0];
    const float* x_item = (const float*)d_in[1];
    const int* ei_rates = (const int*)d_in[2];   // [2, E]
    const int* ei_rev   = (const int*)d_in[3];
    const float* puw = (const float*)d_in[4];
    const float* pub = (const float*)d_in[5];
    const float* piw = (const float*)d_in[6];
    const float* pib = (const float*)d_in[7];
    const float* lnug = (const float*)d_in[8];
    const float* lnub = (const float*)d_in[9];
    const float* lnig = (const float*)d_in[10];
    const float* lnib = (const float*)d_in[11];

    int N = in_sizes[0] / IN_DIM;    // 100000
    int E = in_sizes[2] / 2;         // 600000
    float* out = (float*)d_out;

    dim3 gGemm((N + 127) / 128);
    int scatterBlocks = (E * 32 + 255) / 256;
    int rinvBlocks = (N + 255) / 256;
    int lnBlocks = (N + 7) / 8;

    // input projections (relu)
    proj_gemm_kernel<<<gGemm, 256>>>(x_user, puw, pub, N, 1);
    proj_gemm_kernel<<<gGemm, 256>>>(x_item, piw, pib, N, 0);

    for (int l = 0; l < 2; l++) {
        const float* rwl = (const float*)d_in[12 + l * 6 + 0];
        const float* rbl = (const float*)d_in[12 + l * 6 + 1];
        const float* rwr = (const float*)d_in[12 + l * 6 + 2];
        const float* vwl = (const float*)d_in[12 + l * 6 + 3];
        const float* vbl = (const float*)d_in[12 + l * 6 + 4];
        const float* vwr = (const float*)d_in[12 + l * 6 + 5];

        zero_layer_kernel<<<2048, 256>>>();
        scatter_kernel<<<scatterBlocks, 256>>>(ei_rates, ei_rates + E, E, 1); // user -> item
        scatter_kernel<<<scatterBlocks, 256>>>(ei_rev, ei_rev + E, E, 0);     // item -> user
        rinv_kernel<<<rinvBlocks, 256>>>(N);

        sage_gemm_kernel<<<gGemm, 256>>>(rwl, rwr, rbl, N, 1);  // out_item
        sage_gemm_kernel<<<gGemm, 256>>>(vwl, vwr, vbl, N, 0);  // out_user

        int relu = (l == 0) ? 1 : 0;
        float* ou = (l == 1) ? out : (float*)0;
        float* oi = (l == 1) ? out + (size_t)N * HD : (float*)0;
        ln_kernel<<<lnBlocks, 256>>>(lnug, lnub, ou, N, relu, 1);
        ln_kernel<<<lnBlocks, 256>>>(lnig, lnib, oi, N, relu, 0);
    }
}

// round 2
// speedup vs baseline: 1.7300x; 1.7300x over previous
#include <cuda_runtime.h>
#include <mma.h>

using namespace nvcuda;

#define N_NODES 100000
#define HD 128
#define IN_DIM 256
#define LN_EPS 1e-5f

#define TS 40      // smem tile stride (floats), multiple of 4 for tf32 frags
#define CS 132     // epilogue C stride (floats), multiple of 4

// ---------------- scratch (device globals; no allocation allowed) ----------------
__device__ __align__(16) float g_hu[(size_t)N_NODES * HD];
__device__ __align__(16) float g_hi[(size_t)N_NODES * HD];
__device__ __align__(16) float g_agg_u[(size_t)N_NODES * HD];
__device__ __align__(16) float g_agg_i[(size_t)N_NODES * HD];
__device__ __align__(16) float g_cnt_u[N_NODES];
__device__ __align__(16) float g_cnt_i[N_NODES];

typedef wmma::fragment<wmma::matrix_a, 16, 16, 8, wmma::precision::tf32, wmma::row_major> FragA;
typedef wmma::fragment<wmma::matrix_b, 16, 16, 8, wmma::precision::tf32, wmma::col_major> FragB;
typedef wmma::fragment<wmma::accumulator, 16, 16, 8, float> FragC;

template <class F>
__device__ __forceinline__ void split_frag(F& hi, F& lo, const F& raw) {
#pragma unroll
    for (int e = 0; e < raw.num_elements; e++) {
        float x = raw.x[e];
        float h = wmma::__float_to_tf32(x);
        hi.x[e] = h;
        lo.x[e] = wmma::__float_to_tf32(x - h);
    }
}

__device__ __forceinline__ void mma3(FragC& acc, const FragA& ah, const FragA& al,
                                     const FragB& bh, const FragB& bl) {
    wmma::mma_sync(acc, ah, bh, acc);
    wmma::mma_sync(acc, al, bh, acc);
    wmma::mma_sync(acc, ah, bl, acc);
}

// ---------------- zero agg/cnt for a layer ----------------
__global__ void zero_layer_kernel() {
    const size_t n4 = (size_t)N_NODES * HD / 4;
    const float4 z = make_float4(0.f, 0.f, 0.f, 0.f);
    float4* au = (float4*)g_agg_u;
    float4* ai = (float4*)g_agg_i;
    float4* cu = (float4*)g_cnt_u;
    float4* ci = (float4*)g_cnt_i;
    size_t stride = (size_t)gridDim.x * blockDim.x;
    for (size_t i = (size_t)blockIdx.x * blockDim.x + threadIdx.x; i < n4; i += stride) {
        au[i] = z;
        ai[i] = z;
        if (i < N_NODES / 4) { cu[i] = z; ci[i] = z; }
    }
}

// ---------------- edge scatter: warp per edge, vector RED per lane ----------------
__global__ __launch_bounds__(256) void scatter_kernel(
    const int* __restrict__ src, const int* __restrict__ dst, int E, int to_item)
{
    const float* h = to_item ? g_hu : g_hi;   // source features
    float* agg     = to_item ? g_agg_i : g_agg_u;
    float* cnt     = to_item ? g_cnt_i : g_cnt_u;

    int w = (blockIdx.x * blockDim.x + threadIdx.x) >> 5;
    int lane = threadIdx.x & 31;
    if (w >= E) return;
    int s = src[w];
    int d = dst[w];
    float4 v = ((const float4*)(h + (size_t)s * HD))[lane];
    float* ap = agg + (size_t)d * HD + lane * 4;
    asm volatile("red.global.add.v4.f32 [%0], {%1, %2, %3, %4};"
                 :: "l"(ap), "f"(v.x), "f"(v.y), "f"(v.z), "f"(v.w) : "memory");
    if (lane == 0) atomicAdd(cnt + d, 1.0f);
}

// ---------------- input projection: C = relu(A[N,256] @ W[128,256]^T + b) ----------
// 128x128 block tile, BK=32, 8 warps (2x4), tf32 mma with 3x split
__global__ __launch_bounds__(256, 2) void proj_mma_kernel(
    const float* __restrict__ A, const float* __restrict__ W,
    const float* __restrict__ bias, int N, int to_user)
{
    extern __shared__ float sm[];
    float* As = sm;                 // [128][TS]
    float* Ws = sm + 128 * TS;      // [128][TS]
    float* Cs = sm;                 // [128][CS] (epilogue reuse)

    float* C = to_user ? g_hu : g_hi;
    int tid = threadIdx.x;
    int row0 = blockIdx.x * 128;
    int wid = tid >> 5;
    int warp_m = wid & 1;           // 64-row half
    int warp_n = wid >> 1;          // 32-col quarter

    FragC acc[4][2];
#pragma unroll
    for (int mt = 0; mt < 4; mt++)
#pragma unroll
        for (int nt = 0; nt < 2; nt++) wmma::fill_fragment(acc[mt][nt], 0.f);

    for (int k0 = 0; k0 < IN_DIM; k0 += 32) {
#pragma unroll
        for (int i = 0; i < 4; i++) {
            int idx = tid + i * 256;
            int r = idx >> 3;
            int q = idx & 7;
            int gr = row0 + r;
            float4 v = (gr < N) ? *(const float4*)(A + (size_t)gr * IN_DIM + k0 + q * 4)
                                : make_float4(0.f, 0.f, 0.f, 0.f);
            *(float4*)&As[r * TS + q * 4] = v;
            float4 w = *(const float4*)(W + (size_t)r * IN_DIM + k0 + q * 4);
            *(float4*)&Ws[r * TS + q * 4] = w;
        }
        __syncthreads();
#pragma unroll
        for (int kk = 0; kk < 32; kk += 8) {
            FragB bh[2], bl[2];
#pragma unroll
            for (int nt = 0; nt < 2; nt++) {
                FragB braw;
                wmma::load_matrix_sync(braw, &Ws[(warp_n * 32 + nt * 16) * TS + kk], TS);
                split_frag(bh[nt], bl[nt], braw);
            }
#pragma unroll
            for (int mt = 0; mt < 4; mt++) {
                FragA araw, ah, al;
                wmma::load_matrix_sync(araw, &As[(warp_m * 64 + mt * 16) * TS + kk], TS);
                split_frag(ah, al, araw);
#pragma unroll
                for (int nt = 0; nt < 2; nt++) mma3(acc[mt][nt], ah, al, bh[nt], bl[nt]);
            }
        }
        __syncthreads();
    }

    // epilogue: bias + relu
#pragma unroll
    for (int mt = 0; mt < 4; mt++)
#pragma unroll
        for (int nt = 0; nt < 2; nt++)
            wmma::store_matrix_sync(&Cs[(warp_m * 64 + mt * 16) * CS + warp_n * 32 + nt * 16],
                                    acc[mt][nt], CS, wmma::mem_row_major);
    __syncthreads();
#pragma unroll
    for (int i = 0; i < 16; i++) {
        int idx = tid + i * 256;
        int r = idx >> 5;
        int c4 = idx & 31;
        int gr = row0 + r;
        if (gr < N) {
            float4 v = *(float4*)&Cs[r * CS + c4 * 4];
            float4 b = *(const float4*)(bias + c4 * 4);
            v.x = fmaxf(v.x + b.x, 0.f);
            v.y = fmaxf(v.y + b.y, 0.f);
            v.z = fmaxf(v.z + b.z, 0.f);
            v.w = fmaxf(v.w + b.w, 0.f);
            *(float4*)(C + (size_t)gr * HD + c4 * 4) = v;
        }
    }
}

// ---------------- SAGE combine + residual + LN (+relu), fully fused ----------------
// C = LN(h + (agg*rinv) @ WL^T + h @ WR^T + BL)
__global__ __launch_bounds__(256, 2) void sage_mma_kernel(
    const float* __restrict__ WL, const float* __restrict__ WR,
    const float* __restrict__ BL,
    const float* __restrict__ gamma, const float* __restrict__ beta,
    float* final_out, int N, int to_item, int relu)
{
    extern __shared__ float sm[];
    float* As = sm;
    float* Ws = sm + 128 * TS;
    float* Cs = sm;

    const float* A0  = to_item ? g_agg_i : g_agg_u;
    const float* CNT = to_item ? g_cnt_i : g_cnt_u;
    float* H         = to_item ? g_hi : g_hu;

    int tid = threadIdx.x;
    int row0 = blockIdx.x * 128;
    int wid = tid >> 5;
    int lane = tid & 31;
    int warp_m = wid & 1;
    int warp_n = wid >> 1;

    FragC acc[4][2];
#pragma unroll
    for (int mt = 0; mt < 4; mt++)
#pragma unroll
        for (int nt = 0; nt < 2; nt++) wmma::fill_fragment(acc[mt][nt], 0.f);

    for (int k0 = 0; k0 < 256; k0 += 32) {
#pragma unroll
        for (int i = 0; i < 4; i++) {
            int idx = tid + i * 256;
            int r = idx >> 3;
            int q = idx & 7;
            int gr = row0 + r;
            float4 v, w;
            if (k0 < 128) {
                int c = k0 + q * 4;
                if (gr < N) {
                    v = *(const float4*)(A0 + (size_t)gr * HD + c);
                    float s = 1.0f / fmaxf(CNT[gr], 1.0f);
                    v.x *= s; v.y *= s; v.z *= s; v.w *= s;
                } else v = make_float4(0.f, 0.f, 0.f, 0.f);
                w = *(const float4*)(WL + (size_t)r * HD + c);
            } else {
                int c = k0 - 128 + q * 4;
                v = (gr < N) ? *(const float4*)(H + (size_t)gr * HD + c)
                             : make_float4(0.f, 0.f, 0.f, 0.f);
                w = *(const float4*)(WR + (size_t)r * HD + c);
            }
            *(float4*)&As[r * TS + q * 4] = v;
            *(float4*)&Ws[r * TS + q * 4] = w;
        }
        __syncthreads();
#pragma unroll
        for (int kk = 0; kk < 32; kk += 8) {
            FragB bh[2], bl[2];
#pragma unroll
            for (int nt = 0; nt < 2; nt++) {
                FragB braw;
                wmma::load_matrix_sync(braw, &Ws[(warp_n * 32 + nt * 16) * TS + kk], TS);
                split_frag(bh[nt], bl[nt], braw);
            }
#pragma unroll
            for (int mt = 0; mt < 4; mt++) {
                FragA araw, ah, al;
                wmma::load_matrix_sync(araw, &As[(warp_m * 64 + mt * 16) * TS + kk], TS);
                split_frag(ah, al, araw);
#pragma unroll
                for (int nt = 0; nt < 2; nt++) mma3(acc[mt][nt], ah, al, bh[nt], bl[nt]);
            }
        }
        __syncthreads();
    }

    // stash GEMM result to smem
#pragma unroll
    for (int mt = 0; mt < 4; mt++)
#pragma unroll
        for (int nt = 0; nt < 2; nt++)
            wmma::store_matrix_sync(&Cs[(warp_m * 64 + mt * 16) * CS + warp_n * 32 + nt * 16],
                                    acc[mt][nt], CS, wmma::mem_row_major);
    __syncthreads();

    // fused residual + LN (+relu). Each warp owns rows wid, wid+8, ...
    float4 bv = *(const float4*)(BL + lane * 4);
    float4 gv = *(const float4*)(gamma + lane * 4);
    float4 btv = *(const float4*)(beta + lane * 4);
#pragma unroll
    for (int rr = wid; rr < 128; rr += 8) {
        int gr = row0 + rr;
        if (gr >= N) continue;
        float4 cvv = *(float4*)&Cs[rr * CS + lane * 4];
        float4 hv = *(const float4*)(H + (size_t)gr * HD + lane * 4);
        float v0 = cvv.x + bv.x + hv.x;
        float v1 = cvv.y + bv.y + hv.y;
        float v2 = cvv.z + bv.z + hv.z;
        float v3 = cvv.w + bv.w + hv.w;

        float s = v0 + v1 + v2 + v3;
#pragma unroll
        for (int off = 16; off; off >>= 1) s += __shfl_xor_sync(0xffffffffu, s, off);
        float mu = s * (1.0f / 128.0f);
        v0 -= mu; v1 -= mu; v2 -= mu; v3 -= mu;

        float q = v0 * v0 + v1 * v1 + v2 * v2 + v3 * v3;
#pragma unroll
        for (int off = 16; off; off >>= 1) q += __shfl_xor_sync(0xffffffffu, q, off);
        float rs = rsqrtf(q * (1.0f / 128.0f) + LN_EPS);

        float o0 = v0 * rs * gv.x + btv.x;
        float o1 = v1 * rs * gv.y + btv.y;
        float o2 = v2 * rs * gv.z + btv.z;
        float o3 = v3 * rs * gv.w + btv.w;
        if (relu) {
            o0 = fmaxf(o0, 0.f); o1 = fmaxf(o1, 0.f);
            o2 = fmaxf(o2, 0.f); o3 = fmaxf(o3, 0.f);
        }
        float* dst = final_out ? (final_out + (size_t)gr * HD) : (H + (size_t)gr * HD);
        ((float4*)dst)[lane] = make_float4(o0, o1, o2, o3);
    }
}

// ---------------- launch ----------------
extern "C" void kernel_launch(void* const* d_in, const int* in_sizes, int n_in,
                              void* d_out, int out_size)
{
    const float* x_user = (const float*)d_in[0];
    const float* x_item = (const float*)d_in[1];
    const int* ei_rates = (const int*)d_in[2];   // [2, E]
    const int* ei_rev   = (const int*)d_in[3];
    const float* puw = (const float*)d_in[4];
    const float* pub = (const float*)d_in[5];
    const float* piw = (const float*)d_in[6];
    const float* pib = (const float*)d_in[7];
    const float* lnug = (const float*)d_in[8];
    const float* lnub = (const float*)d_in[9];
    const float* lnig = (const float*)d_in[10];
    const float* lnib = (const float*)d_in[11];

    int N = in_sizes[0] / IN_DIM;    // 100000
    int E = in_sizes[2] / 2;         // 600000
    float* out = (float*)d_out;

    const int SMEM = 128 * CS * sizeof(float);   // 67584 B (covers tile smem too)
    static int configured = 0;
    if (!configured) {
        cudaFuncSetAttribute(proj_mma_kernel, cudaFuncAttributeMaxDynamicSharedMemorySize, SMEM);
        cudaFuncSetAttribute(sage_mma_kernel, cudaFuncAttributeMaxDynamicSharedMemorySize, SMEM);
        configured = 1;
    }

    dim3 gGemm((N + 127) / 128);
    int scatterBlocks = (E * 32 + 255) / 256;

    proj_mma_kernel<<<gGemm, 256, SMEM>>>(x_user, puw, pub, N, 1);
    proj_mma_kernel<<<gGemm, 256, SMEM>>>(x_item, piw, pib, N, 0);

    for (int l = 0; l < 2; l++) {
        const float* rwl = (const float*)d_in[12 + l * 6 + 0];
        const float* rbl = (const float*)d_in[12 + l * 6 + 1];
        const float* rwr = (const float*)d_in[12 + l * 6 + 2];
        const float* vwl = (const float*)d_in[12 + l * 6 + 3];
        const float* vbl = (const float*)d_in[12 + l * 6 + 4];
        const float* vwr = (const float*)d_in[12 + l * 6 + 5];

        zero_layer_kernel<<<2048, 256>>>();
        scatter_kernel<<<scatterBlocks, 256>>>(ei_rates, ei_rates + E, E, 1); // user -> item
        scatter_kernel<<<scatterBlocks, 256>>>(ei_rev, ei_rev + E, E, 0);     // item -> user

        int relu = (l == 0) ? 1 : 0;
        float* ou = (l == 1) ? out : (float*)0;
        float* oi = (l == 1) ? out + (size_t)N * HD : (float*)0;
        // item side: agg over rates edges, combine with g_hi
        sage_mma_kernel<<<gGemm, 256, SMEM>>>(rwl, rwr, rbl, lnig, lnib, oi, N, 1, relu);
        // user side: agg over rev edges, combine with g_hu
        sage_mma_kernel<<<gGemm, 256, SMEM>>>(vwl, vwr, vbl, lnug, lnub, ou, N, 0, relu);
    }
}